// round 8
// baseline (speedup 1.0000x reference)
#include <cuda_runtime.h>
#include <cstdint>

#define HWPIX 3136
#define NELEM 51380224
#define TFAC 0.05f
#define QMAX 32639.f

__device__ __align__(256) unsigned short g_xq[NELEM];  // x NHWC packed (hi8,lo8)
__device__ __align__(256) unsigned short g_aq[NELEM];  // act1 NHWC packed
__device__ float g_buf1[NELEM], g_buf2[NELEM];         // conv outs NHWC fp32
__device__ __align__(256) char g_ws[2][9][65536];      // sign weights [pos][co*256+ci]
__device__ unsigned g_absw[2], g_absx;
__device__ double g_wsum[2];
__device__ unsigned long long g_wcnt[2];
__device__ double g_bnsum[2][256], g_bnsq[2][256];
__device__ float g_bnscale[2][256], g_bnshift[2][256];
__device__ unsigned g_vmax[256], g_vmin[256];
__device__ float g_ainv, g_as;

__device__ __forceinline__ unsigned encf(float f) {
    unsigned u = __float_as_uint(f);
    return (u & 0x80000000u) ? ~u : (u | 0x80000000u);
}
__device__ __forceinline__ float decf(unsigned u) {
    return __uint_as_float((u & 0x80000000u) ? (u & 0x7FFFFFFFu) : ~u);
}
__device__ __forceinline__ void imma(int* d, const unsigned* a, const unsigned* b) {
    asm volatile(
        "mma.sync.aligned.m16n8k32.row.col.s32.s8.s8.s32 "
        "{%0,%1,%2,%3}, {%4,%5,%6,%7}, {%8,%9}, {%0,%1,%2,%3};"
        : "+r"(d[0]), "+r"(d[1]), "+r"(d[2]), "+r"(d[3])
        : "r"(a[0]), "r"(a[1]), "r"(a[2]), "r"(a[3]), "r"(b[0]), "r"(b[1]));
}
__device__ __forceinline__ unsigned short pack_q(int q) {
    int hi = (q + 128) >> 8;
    return (unsigned short)((hi & 0xFF) | ((q - (hi << 8)) << 8));
}

// ---------------- prep kernels -------------------------------------------------
__global__ void init_k() {
    int t = threadIdx.x;
    if (t < 2) { g_absw[t] = 0u; g_wsum[t] = 0.0; g_wcnt[t] = 0ull; }
    if (t == 2) g_absx = 0u;
    g_bnsum[0][t] = 0.0; g_bnsum[1][t] = 0.0;
    g_bnsq[0][t] = 0.0;  g_bnsq[1][t] = 0.0;
    g_vmax[t] = 0u; g_vmin[t] = 0xFFFFFFFFu;
}

// sel: 0 -> g_absw[0], 1 -> g_absw[1], 2 -> g_absx   (device-side resolve!)
__global__ void absmax_k(const float* __restrict__ p, size_t n, int sel) {
    float m = 0.f;
    for (size_t i = (size_t)blockIdx.x * blockDim.x + threadIdx.x; i < n;
         i += (size_t)gridDim.x * blockDim.x)
        m = fmaxf(m, fabsf(p[i]));
#pragma unroll
    for (int o = 16; o; o >>= 1) m = fmaxf(m, __shfl_xor_sync(~0u, m, o));
    __shared__ float sm[8];
    if ((threadIdx.x & 31) == 0) sm[threadIdx.x >> 5] = m;
    __syncthreads();
    if (threadIdx.x == 0) {
        float mm = sm[0];
#pragma unroll
        for (int i = 1; i < 8; i++) mm = fmaxf(mm, sm[i]);
        unsigned* dst = (sel == 2) ? &g_absx : &g_absw[sel];
        atomicMax(dst, __float_as_uint(mm));
    }
}

__global__ void wsum_k(const float* __restrict__ w, int sel) {
    float th = TFAC * __uint_as_float(g_absw[sel]);
    double s = 0.0;
    unsigned c = 0;
    for (int i = blockIdx.x * blockDim.x + threadIdx.x; i < 589824;
         i += gridDim.x * blockDim.x) {
        float v = w[i];
        if (v >= th || v <= -th) { s += (double)fabsf(v); c++; }
    }
#pragma unroll
    for (int o = 16; o; o >>= 1) {
        s += __shfl_xor_sync(~0u, s, o);
        c += __shfl_xor_sync(~0u, c, o);
    }
    __shared__ double ss[8];
    __shared__ unsigned sc_[8];
    if ((threadIdx.x & 31) == 0) { ss[threadIdx.x >> 5] = s; sc_[threadIdx.x >> 5] = c; }
    __syncthreads();
    if (threadIdx.x == 0) {
        double S = 0.0; unsigned long long C = 0ull;
#pragma unroll
        for (int i = 0; i < 8; i++) { S += ss[i]; C += sc_[i]; }
        atomicAdd(&g_wsum[sel], S);
        atomicAdd(&g_wcnt[sel], C);
    }
}

__global__ void wsign_k(const float* __restrict__ w, int sel) {
    int i = blockIdx.x * 256 + threadIdx.x;
    float th = TFAC * __uint_as_float(g_absw[sel]);
#pragma unroll
    for (int k = 0; k < 9; k++) {
        float v = w[(size_t)i * 9 + k];
        g_ws[sel][k][i] = (v >= th) ? (char)1 : ((v < -th) ? (char)-1 : (char)0);
    }
}

__global__ void xprep_k(const float* __restrict__ x) {
    __shared__ float s[32][33];
    int img = blockIdx.z, c0 = blockIdx.y * 32, p0 = blockIdx.x * 32;
    int tx = threadIdx.x, ty = threadIdx.y;
    float xm = __uint_as_float(g_absx);
    float inv = (xm > 0.f) ? QMAX / xm : 0.f;
#pragma unroll
    for (int r = 0; r < 4; r++)
        s[ty + r * 8][tx] = x[((size_t)img * 256 + c0 + ty + r * 8) * HWPIX + p0 + tx];
    __syncthreads();
#pragma unroll
    for (int r = 0; r < 4; r++) {
        int q = __float2int_rn(s[tx][ty + r * 8] * inv);
        q = max(-32639, min(32639, q));
        g_xq[((size_t)img * HWPIX + p0 + ty + r * 8) * 256 + c0 + tx] = pack_q(q);
    }
}

// ---------------- int8 conv -----------------------------------------------------
// CTA 128co x 128pix (2 rows x 64 cols), 8 warps 64co x 32pix.
// 8 ci-chunks of 32. smem: Bhi[260x48] Blo[260x48] A[9][128][48].
#define SBLO 12480
#define SA   24960
#define SMSZ 80256

__global__ void __launch_bounds__(256, 1) conv_k(int which) {
    extern __shared__ char smc[];
    const int tid = threadIdx.x, lane = tid & 31, warp = tid >> 5;
    const int g = lane >> 2, tg = lane & 3;
    const int wco = (warp >> 2) * 64, wpix = (warp & 3) * 32;
    const int h0 = blockIdx.x * 2, co0 = blockIdx.y * 128, img = blockIdx.z;
    const unsigned short* __restrict__ xq = which ? g_aq : g_xq;
    float* __restrict__ out = which ? g_buf2 : g_buf1;

    int acch[4][4][4], accl[4][4][4];
#pragma unroll
    for (int a = 0; a < 4; a++)
#pragma unroll
        for (int b = 0; b < 4; b++)
#pragma unroll
            for (int c = 0; c < 4; c++) { acch[a][b][c] = 0; accl[a][b][c] = 0; }

#pragma unroll 1
    for (int ch = 0; ch < 8; ch++) {
        const int ci0 = ch * 32;
        if (ch) __syncthreads();
        // B: 256 rows, 1 thread/row; split packed shorts into hi/lo planes
        {
            int r = tid, ih = h0 - 1 + (r >> 6), iw = (r & 63) - 1;
            unsigned u[16];
            if ((unsigned)ih < 56u && (unsigned)iw < 56u) {
                const uint4* p =
                    (const uint4*)(xq + ((size_t)img * HWPIX + ih * 56 + iw) * 256 + ci0);
#pragma unroll
                for (int i = 0; i < 4; i++) {
                    uint4 v = p[i];
                    u[4 * i] = v.x; u[4 * i + 1] = v.y;
                    u[4 * i + 2] = v.z; u[4 * i + 3] = v.w;
                }
            } else {
#pragma unroll
                for (int i = 0; i < 16; i++) u[i] = 0u;
            }
            uint4 hv, lv;
#pragma unroll
            for (int hf = 0; hf < 2; hf++) {
                const unsigned* q = u + 8 * hf;
                hv.x = __byte_perm(q[0], q[1], 0x6420);
                hv.y = __byte_perm(q[2], q[3], 0x6420);
                hv.z = __byte_perm(q[4], q[5], 0x6420);
                hv.w = __byte_perm(q[6], q[7], 0x6420);
                lv.x = __byte_perm(q[0], q[1], 0x7531);
                lv.y = __byte_perm(q[2], q[3], 0x7531);
                lv.z = __byte_perm(q[4], q[5], 0x7531);
                lv.w = __byte_perm(q[6], q[7], 0x7531);
                *(uint4*)(smc + r * 48 + hf * 16) = hv;
                *(uint4*)(smc + SBLO + r * 48 + hf * 16) = lv;
            }
            if (tid < 8) {   // zero halo-spill rows 256..259
                uint4 z = make_uint4(0, 0, 0, 0);
                int rr = 256 + (tid >> 1), off = (tid & 1) * 16;
                *(uint4*)(smc + rr * 48 + off) = z;
                *(uint4*)(smc + SBLO + rr * 48 + off) = z;
            }
        }
        // A: all 9 positions, 9*128*32B
#pragma unroll
        for (int t = 0; t < 9; t++) {
            int idx = tid + t * 256;
            int pos = idx >> 8, r = (idx & 255) >> 1, hf = idx & 1;
            uint4 v = *(const uint4*)(g_ws[which][pos] +
                                      (size_t)(co0 + r) * 256 + ci0 + hf * 16);
            *(uint4*)(smc + SA + pos * 6144 + r * 48 + hf * 16) = v;
        }
        __syncthreads();

#pragma unroll 1
        for (int pos = 0; pos < 9; pos++) {
            const int dlt = (pos / 3) * 64 + (pos % 3);
            const char* ap = smc + SA + pos * 6144;
            unsigned a[4][4];
#pragma unroll
            for (int mt = 0; mt < 4; mt++) {
                const char* p = ap + (wco + mt * 16 + g) * 48 + tg * 4;
                a[mt][0] = *(const unsigned*)p;
                a[mt][1] = *(const unsigned*)(p + 8 * 48);
                a[mt][2] = *(const unsigned*)(p + 16);
                a[mt][3] = *(const unsigned*)(p + 8 * 48 + 16);
            }
#pragma unroll
            for (int nt = 0; nt < 4; nt++) {
                const char* bp = smc + (wpix + nt * 8 + g + dlt) * 48 + tg * 4;
                unsigned bh[2], bl[2];
                bh[0] = *(const unsigned*)bp;
                bh[1] = *(const unsigned*)(bp + 16);
                bl[0] = *(const unsigned*)(bp + SBLO);
                bl[1] = *(const unsigned*)(bp + SBLO + 16);
#pragma unroll
                for (int mt = 0; mt < 4; mt++) imma(acch[mt][nt], a[mt], bh);
#pragma unroll
                for (int mt = 0; mt < 4; mt++) imma(accl[mt][nt], a[mt], bl);
            }
        }
    }

    // epilogue: v = 256*hi + lo, NHWC fp32
#pragma unroll
    for (int mt = 0; mt < 4; mt++) {
        int co = co0 + wco + mt * 16 + g;
#pragma unroll
        for (int nt = 0; nt < 4; nt++) {
            int n = wpix + nt * 8 + tg * 2;
            int ow = n & 63;
            if (ow < 56) {
                size_t p = ((size_t)img * HWPIX + (h0 + (n >> 6)) * 56 + ow) * 256;
                out[p + co] = fmaf(256.f, (float)acch[mt][nt][0], (float)accl[mt][nt][0]);
                out[p + co + 8] = fmaf(256.f, (float)acch[mt][nt][2], (float)accl[mt][nt][2]);
                out[p + 256 + co] = fmaf(256.f, (float)acch[mt][nt][1], (float)accl[mt][nt][1]);
                out[p + 256 + co + 8] = fmaf(256.f, (float)acch[mt][nt][3], (float)accl[mt][nt][3]);
            }
        }
    }
}

// ---------------- BN -------------------------------------------------------------
__global__ void bnstat_k(int which) {
    const float* __restrict__ v = which ? g_buf2 : g_buf1;
    int c = threadIdx.x;
    const float* p = v + (size_t)blockIdx.x * 784 * 256 + c;
    double s = 0.0, qq = 0.0;
    float mx = -3.4e38f, mn = 3.4e38f;
#pragma unroll 4
    for (int i = 0; i < 784; i++) {
        float f = p[(size_t)i * 256];
        s += (double)f; qq += (double)f * f;
        mx = fmaxf(mx, f); mn = fminf(mn, f);
    }
    atomicAdd(&g_bnsum[which][c], s);
    atomicAdd(&g_bnsq[which][c], qq);
    if (which == 0) {
        atomicMax(&g_vmax[c], encf(mx));
        atomicMin(&g_vmin[c], encf(mn));
    }
}

__global__ void bnfin_k(const float* __restrict__ gamma,
                        const float* __restrict__ beta, int which) {
    __shared__ float red[256];
    int c = threadIdx.x;
    double mean = g_bnsum[which][c] / 200704.0;
    double var = g_bnsq[which][c] / 200704.0 - mean * mean;
    if (var < 0.0) var = 0.0;
    unsigned long long wc = g_wcnt[which];
    if (!wc) wc = 1ull;
    double W = g_wsum[which] / (double)wc;
    if (W < 1e-300) W = 1e-300;
    float xm = __uint_as_float(g_absx);
    double s = which ? (double)g_as : (double)(xm > 0.f ? xm : 1.f) / 32639.0;
    double f = W * s;
    double inv = 1.0 / sqrt(var + 1e-5 / (f * f));
    float sc = gamma[c] * (float)inv;
    float sh = beta[c] - (float)(mean * inv) * gamma[c];
    g_bnscale[which][c] = sc;
    g_bnshift[which][c] = sh;
    if (which == 0) {
        red[c] = fmaxf(fmaxf(sc * decf(g_vmax[c]) + sh, sc * decf(g_vmin[c]) + sh), 0.f);
        __syncthreads();
        for (int o = 128; o; o >>= 1) {
            if (c < o) red[c] = fmaxf(red[c], red[c + o]);
            __syncthreads();
        }
        if (c == 0) {
            float A = red[0];
            g_ainv = (A > 0.f) ? QMAX / A : 0.f;
            g_as = (A > 0.f) ? A / QMAX : 1.f;
        }
    }
}

__global__ void actprep_k() {   // BN1+ReLU+quantize: g_buf1 -> g_aq
    size_t i4 = (size_t)blockIdx.x * 256 + threadIdx.x;
    int c0 = ((int)(i4 & 63)) * 4;
    float4 v = ((const float4*)g_buf1)[i4];
    float4 sc = *(const float4*)&g_bnscale[0][c0];
    float4 sh = *(const float4*)&g_bnshift[0][c0];
    float inv = g_ainv;
    int q0 = min(__float2int_rn(fmaxf(fmaf(v.x, sc.x, sh.x), 0.f) * inv), 32639);
    int q1 = min(__float2int_rn(fmaxf(fmaf(v.y, sc.y, sh.y), 0.f) * inv), 32639);
    int q2 = min(__float2int_rn(fmaxf(fmaf(v.z, sc.z, sh.z), 0.f) * inv), 32639);
    int q3 = min(__float2int_rn(fmaxf(fmaf(v.w, sc.w, sh.w), 0.f) * inv), 32639);
    ((uint2*)g_aq)[i4] = make_uint2(pack_q(q0) | ((unsigned)pack_q(q1) << 16),
                                    pack_q(q2) | ((unsigned)pack_q(q3) << 16));
}

__global__ void final_k(const float* __restrict__ x, float* __restrict__ out) {
    __shared__ float s[32][33];
    int img = blockIdx.z, c0 = blockIdx.y * 32, p0 = blockIdx.x * 32;
    int tx = threadIdx.x, ty = threadIdx.y;
#pragma unroll
    for (int r = 0; r < 4; r++) {
        int pl = ty + r * 8;
        float v = g_buf2[((size_t)img * HWPIX + p0 + pl) * 256 + c0 + tx];
        s[pl][tx] = fmaf(v, g_bnscale[1][c0 + tx], g_bnshift[1][c0 + tx]);
    }
    __syncthreads();
#pragma unroll
    for (int r = 0; r < 4; r++) {
        int cl = ty + r * 8;
        size_t o = ((size_t)img * 256 + c0 + cl) * HWPIX + p0 + tx;
        out[o] = fmaxf(s[tx][cl] + x[o], 0.f);
    }
}

// ----------------------------------------------------------------------------------
extern "C" void kernel_launch(void* const* d_in, const int* in_sizes, int n_in,
                              void* d_out, int out_size) {
    const float* x  = (const float*)d_in[0];
    const float* w1 = (const float*)d_in[1];
    const float* g1 = (const float*)d_in[2];
    const float* b1 = (const float*)d_in[3];
    const float* w2 = (const float*)d_in[4];
    const float* g2 = (const float*)d_in[5];
    const float* b2 = (const float*)d_in[6];
    float* out = (float*)d_out;

    cudaFuncSetAttribute(conv_k, cudaFuncAttributeMaxDynamicSharedMemorySize, SMSZ);

    init_k<<<1, 256>>>();
    absmax_k<<<256, 256>>>(w1, 589824, 0);
    absmax_k<<<256, 256>>>(w2, 589824, 1);
    absmax_k<<<512, 256>>>(x, NELEM, 2);
    wsum_k<<<256, 256>>>(w1, 0);
    wsum_k<<<256, 256>>>(w2, 1);
    wsign_k<<<256, 256>>>(w1, 0);
    wsign_k<<<256, 256>>>(w2, 1);

    xprep_k<<<dim3(98, 8, 64), dim3(32, 8)>>>(x);

    dim3 cgrid(28, 2, 64);
    conv_k<<<cgrid, 256, SMSZ>>>(0);
    bnstat_k<<<256, 256>>>(0);
    bnfin_k<<<1, 256>>>(g1, b1, 0);
    actprep_k<<<50176, 256>>>();

    conv_k<<<cgrid, 256, SMSZ>>>(1);
    bnstat_k<<<256, 256>>>(1);
    bnfin_k<<<1, 256>>>(g2, b2, 1);
    final_k<<<dim3(98, 8, 64), dim3(32, 8)>>>(x, out);
}

// round 9
// speedup vs baseline: 2.4093x; 2.4093x over previous
#include <cuda_runtime.h>
#include <cuda_bf16.h>
#include <cstdint>

#define HWPIX 3136
#define NELEM 51380224
#define TFAC 0.05f

__device__ __nv_bfloat16 g_xhi[NELEM], g_xlo[NELEM];
__device__ __nv_bfloat16 g_ahi[NELEM], g_alo[NELEM];
__device__ float g_buf1[NELEM], g_buf2[NELEM];
__device__ __nv_bfloat16 g_ws[2][9][65536];   // sign weights [sel][pos][co*256+ci]
__device__ unsigned g_absw[2], g_absx;
__device__ double g_wsum[2];
__device__ unsigned long long g_wcnt[2];
__device__ double g_bnsum[2][256], g_bnsq[2][256];
__device__ float g_bnscale[2][256], g_bnshift[2][256];

__device__ __forceinline__ void mma16816(float* d, const uint32_t* a,
                                         const uint32_t* b) {
    asm volatile(
        "mma.sync.aligned.m16n8k16.row.col.f32.bf16.bf16.f32 "
        "{%0,%1,%2,%3}, {%4,%5,%6,%7}, {%8,%9}, {%0,%1,%2,%3};"
        : "+f"(d[0]), "+f"(d[1]), "+f"(d[2]), "+f"(d[3])
        : "r"(a[0]), "r"(a[1]), "r"(a[2]), "r"(a[3]), "r"(b[0]), "r"(b[1]));
}

// ---- launch 1: init ----
__global__ void init_k() {
    int t = threadIdx.x;
    if (t < 2) { g_absw[t] = 0u; g_wsum[t] = 0.0; g_wcnt[t] = 0ull; }
    if (t == 2) g_absx = 0u;
    g_bnsum[0][t] = 0.0; g_bnsum[1][t] = 0.0;
    g_bnsq[0][t] = 0.0;  g_bnsq[1][t] = 0.0;
}

// ---- launch 2: absmax of w1 / w2 / x (blockIdx.y selects) ----
__global__ void absmax3_k(const float* __restrict__ w1,
                          const float* __restrict__ w2,
                          const float* __restrict__ x) {
    int sel = blockIdx.y;
    float m = 0.f;
    if (sel < 2) {
        const float* w = sel ? w2 : w1;
        for (int i = blockIdx.x * blockDim.x + threadIdx.x; i < 589824;
             i += gridDim.x * blockDim.x)
            m = fmaxf(m, fabsf(w[i]));
    } else {
        const float4* p = (const float4*)x;
        for (size_t i = (size_t)blockIdx.x * blockDim.x + threadIdx.x;
             i < NELEM / 4; i += (size_t)gridDim.x * blockDim.x) {
            float4 v = p[i];
            m = fmaxf(m, fmaxf(fmaxf(fabsf(v.x), fabsf(v.y)),
                               fmaxf(fabsf(v.z), fabsf(v.w))));
        }
    }
#pragma unroll
    for (int o = 16; o; o >>= 1) m = fmaxf(m, __shfl_xor_sync(~0u, m, o));
    __shared__ float sm[8];
    if ((threadIdx.x & 31) == 0) sm[threadIdx.x >> 5] = m;
    __syncthreads();
    if (threadIdx.x == 0) {
        float mm = sm[0];
#pragma unroll
        for (int i = 1; i < 8; i++) mm = fmaxf(mm, sm[i]);
        atomicMax(sel < 2 ? &g_absw[sel] : &g_absx, __float_as_uint(mm));
    }
}

// ---- launch 3: wsum + wsign + xprep fused (flat 256-thread blocks) ----
__global__ void prep_k(const float* __restrict__ w1, const float* __restrict__ w2,
                       const float* __restrict__ x) {
    int b = blockIdx.x, tid = threadIdx.x;
    if (b < 512) {                       // wsum over w1 / w2
        int sel = b >> 8;
        const float* w = sel ? w2 : w1;
        float th = TFAC * __uint_as_float(g_absw[sel]);
        double s = 0.0;
        unsigned c = 0;
        for (int i = (b & 255) * 256 + tid; i < 589824; i += 65536) {
            float v = w[i];
            if (v >= th || v <= -th) { s += (double)fabsf(v); c++; }
        }
#pragma unroll
        for (int o = 16; o; o >>= 1) {
            s += __shfl_xor_sync(~0u, s, o);
            c += __shfl_xor_sync(~0u, c, o);
        }
        __shared__ double ss[8];
        __shared__ unsigned sc_[8];
        if ((tid & 31) == 0) { ss[tid >> 5] = s; sc_[tid >> 5] = c; }
        __syncthreads();
        if (tid == 0) {
            double S = 0.0; unsigned long long C = 0ull;
#pragma unroll
            for (int i = 0; i < 8; i++) { S += ss[i]; C += sc_[i]; }
            atomicAdd(&g_wsum[sel], S);
            atomicAdd(&g_wcnt[sel], C);
        }
    } else if (b < 1024) {               // wsign
        int sel = (b - 512) >> 8;
        const float* w = sel ? w2 : w1;
        float th = TFAC * __uint_as_float(g_absw[sel]);
        int i = ((b - 512) & 255) * 256 + tid;
#pragma unroll
        for (int k = 0; k < 9; k++) {
            float v = w[(size_t)i * 9 + k];
            float s = (v >= th) ? 1.f : ((v < -th) ? -1.f : 0.f);
            g_ws[sel][k][i] = __float2bfloat16(s);
        }
    } else {                             // xprep: NCHW -> NHWC hi/lo
        __shared__ float s[32][33];
        int idx = b - 1024;              // 64*784 blocks
        int img = idx / 784, rem = idx % 784;
        int c0 = (rem / 98) * 32, p0 = (rem % 98) * 32;
        int tx = tid & 31, ty = tid >> 5;
#pragma unroll
        for (int r = 0; r < 4; r++)
            s[ty + r * 8][tx] =
                x[((size_t)img * 256 + c0 + ty + r * 8) * HWPIX + p0 + tx];
        __syncthreads();
#pragma unroll
        for (int r = 0; r < 4; r++) {
            float v = s[tx][ty + r * 8];
            __nv_bfloat16 h = __float2bfloat16(v);
            __nv_bfloat16 l = __float2bfloat16(v - __bfloat162float(h));
            size_t d = ((size_t)img * HWPIX + p0 + ty + r * 8) * 256 + c0 + tx;
            g_xhi[d] = h; g_xlo[d] = l;
        }
    }
}

// ---- conv: CTA 128co x 128pix, bf16 HMMA, A double-buffered ----
#define SB_LO 20800
#define SA    41600     // bufs at 41600 / 51840, stride 80, 128 rows
#define SMSZ  62080

__device__ __forceinline__ void ldgA(uint4* v, int which, int pos, int co0,
                                     int ci0, int tid) {
    const uint4* p = (const uint4*)(g_ws[which][pos] +
                                    (size_t)(co0 + (tid >> 1)) * 256 + ci0 +
                                    (tid & 1) * 16);
    v[0] = p[0]; v[1] = p[1];
}
__device__ __forceinline__ void stsA(char* base, const uint4* v, int tid) {
    char* d = base + (tid >> 1) * 80 + (tid & 1) * 32;
    *(uint4*)d = v[0];
    *(uint4*)(d + 16) = v[1];
}

__global__ void __launch_bounds__(256, 2) conv_k(int which) {
    extern __shared__ char smc[];
    const int tid = threadIdx.x, lane = tid & 31, warp = tid >> 5;
    const int g = lane >> 2, tg = lane & 3;
    const int wco = (warp >> 2) * 64, wpix = (warp & 3) * 32;
    const int h0 = blockIdx.x * 2, co0 = blockIdx.y * 128, img = blockIdx.z;
    const __nv_bfloat16* __restrict__ xhi = which ? g_ahi : g_xhi;
    const __nv_bfloat16* __restrict__ xlo = which ? g_alo : g_xlo;
    float* __restrict__ out = which ? g_buf2 : g_buf1;

    float acc[4][4][4];
#pragma unroll
    for (int i = 0; i < 4; i++)
#pragma unroll
        for (int j = 0; j < 4; j++)
#pragma unroll
            for (int k = 0; k < 4; k++) acc[i][j][k] = 0.f;

    uint4 apf[2];
#pragma unroll 1
    for (int ch = 0; ch < 8; ch++) {
        const int ci0 = ch * 32;
        __syncthreads();                 // prev chunk readers done
        {                                // B tile: 1 row per thread + halo zero
            int r = tid, ih = h0 - 1 + (r >> 6), iw = (r & 63) - 1;
            uint4 z = make_uint4(0, 0, 0, 0);
            uint4 h0v = z, h1v = z, h2v = z, h3v = z;
            uint4 l0v = z, l1v = z, l2v = z, l3v = z;
            if ((unsigned)ih < 56u && (unsigned)iw < 56u) {
                size_t s = ((size_t)img * HWPIX + ih * 56 + iw) * 256 + ci0;
                const uint4* ph = (const uint4*)(xhi + s);
                const uint4* pl = (const uint4*)(xlo + s);
                h0v = ph[0]; h1v = ph[1]; h2v = ph[2]; h3v = ph[3];
                l0v = pl[0]; l1v = pl[1]; l2v = pl[2]; l3v = pl[3];
            }
            char* bh = smc + r * 80;
            *(uint4*)bh = h0v; *(uint4*)(bh + 16) = h1v;
            *(uint4*)(bh + 32) = h2v; *(uint4*)(bh + 48) = h3v;
            char* bl = smc + SB_LO + r * 80;
            *(uint4*)bl = l0v; *(uint4*)(bl + 16) = l1v;
            *(uint4*)(bl + 32) = l2v; *(uint4*)(bl + 48) = l3v;
            if (tid < 8) {
                int rr = 256 + (tid >> 1), q = (tid & 1) * 32;
                char* zh = smc + rr * 80 + q;
                char* zl = smc + SB_LO + rr * 80 + q;
                *(uint4*)zh = z; *(uint4*)(zh + 16) = z;
                *(uint4*)zl = z; *(uint4*)(zl + 16) = z;
            }
        }
        ldgA(apf, which, 0, co0, ci0, tid);
        stsA(smc + SA, apf, tid);
        __syncthreads();

        int ab = 0;
#pragma unroll 1
        for (int pos = 0; pos < 9; pos++) {
            if (pos < 8) ldgA(apf, which, pos + 1, co0, ci0, tid);
            const int dlt = (pos / 3) * 64 + (pos % 3);
            const char* abase = smc + SA + ab * 10240;
#pragma unroll
            for (int kk = 0; kk < 2; kk++) {
                const int kb = kk * 32 + tg * 4;
                uint32_t a[4][4];
#pragma unroll
                for (int mt = 0; mt < 4; mt++) {
                    const char* ap = abase + (wco + mt * 16 + g) * 80 + kb;
                    a[mt][0] = *(const uint32_t*)ap;
                    a[mt][1] = *(const uint32_t*)(ap + 640);
                    a[mt][2] = *(const uint32_t*)(ap + 16);
                    a[mt][3] = *(const uint32_t*)(ap + 656);
                }
#pragma unroll
                for (int nt = 0; nt < 4; nt++) {
                    const char* bb = smc + (wpix + nt * 8 + g + dlt) * 80 + kb;
                    uint32_t bh[2], bl[2];
                    bh[0] = *(const uint32_t*)bb;
                    bh[1] = *(const uint32_t*)(bb + 16);
                    bl[0] = *(const uint32_t*)(bb + SB_LO);
                    bl[1] = *(const uint32_t*)(bb + SB_LO + 16);
#pragma unroll
                    for (int mt = 0; mt < 4; mt++) mma16816(acc[mt][nt], a[mt], bh);
#pragma unroll
                    for (int mt = 0; mt < 4; mt++) mma16816(acc[mt][nt], a[mt], bl);
                }
            }
            if (pos < 8) {
                stsA(smc + SA + (ab ^ 1) * 10240, apf, tid);
                __syncthreads();
                ab ^= 1;
            }
        }
    }

#pragma unroll
    for (int mt = 0; mt < 4; mt++) {
        int co = co0 + wco + mt * 16 + g;
#pragma unroll
        for (int nt = 0; nt < 4; nt++) {
            int n = wpix + nt * 8 + tg * 2;
            int ow = n & 63;
            if (ow < 56) {
                size_t p = ((size_t)img * HWPIX + (h0 + (n >> 6)) * 56 + ow) * 256;
                out[p + co] = acc[mt][nt][0];
                out[p + co + 8] = acc[mt][nt][2];
                out[p + 256 + co] = acc[mt][nt][1];
                out[p + 256 + co + 8] = acc[mt][nt][3];
            }
        }
    }
}

// ---- BN ----
__global__ void bnstat_k(int which) {
    const float* __restrict__ v = which ? g_buf2 : g_buf1;
    int c = threadIdx.x;
    const float* p = v + (size_t)blockIdx.x * 784 * 256 + c;
    double s = 0.0, qq = 0.0;
#pragma unroll 4
    for (int i = 0; i < 784; i++) {
        double f = (double)p[(size_t)i * 256];
        s += f; qq += f * f;
    }
    atomicAdd(&g_bnsum[which][c], s);
    atomicAdd(&g_bnsq[which][c], qq);
}

__global__ void bnfin_k(const float* __restrict__ gamma,
                        const float* __restrict__ beta, int which) {
    int c = threadIdx.x;
    double mean = g_bnsum[which][c] / 200704.0;
    double var = g_bnsq[which][c] / 200704.0 - mean * mean;
    if (var < 0.0) var = 0.0;
    unsigned long long wc = g_wcnt[which];
    if (!wc) wc = 1ull;
    double W = g_wsum[which] / (double)wc;
    if (W < 1e-300) W = 1e-300;
    double eps = 1e-5 / (W * W);
    float sc = gamma[c] * (float)(1.0 / sqrt(var + eps));
    g_bnscale[which][c] = sc;
    g_bnshift[which][c] = beta[c] - (float)(mean * (1.0 / sqrt(var + eps))) * gamma[c];
}

__global__ void actprep_k() {
    size_t i4 = (size_t)blockIdx.x * 256 + threadIdx.x;
    int c0 = ((int)i4 & 63) * 4;
    float4 v = ((const float4*)g_buf1)[i4];
    float4 sc = *(const float4*)&g_bnscale[0][c0];
    float4 sh = *(const float4*)&g_bnshift[0][c0];
    float a[4];
    a[0] = fmaxf(fmaf(v.x, sc.x, sh.x), 0.f);
    a[1] = fmaxf(fmaf(v.y, sc.y, sh.y), 0.f);
    a[2] = fmaxf(fmaf(v.z, sc.z, sh.z), 0.f);
    a[3] = fmaxf(fmaf(v.w, sc.w, sh.w), 0.f);
    __nv_bfloat162 h0, h1, l0, l1;
    h0.x = __float2bfloat16(a[0]); h0.y = __float2bfloat16(a[1]);
    h1.x = __float2bfloat16(a[2]); h1.y = __float2bfloat16(a[3]);
    l0.x = __float2bfloat16(a[0] - __bfloat162float(h0.x));
    l0.y = __float2bfloat16(a[1] - __bfloat162float(h0.y));
    l1.x = __float2bfloat16(a[2] - __bfloat162float(h1.x));
    l1.y = __float2bfloat16(a[3] - __bfloat162float(h1.y));
    ((__nv_bfloat162*)g_ahi)[i4 * 2] = h0;
    ((__nv_bfloat162*)g_ahi)[i4 * 2 + 1] = h1;
    ((__nv_bfloat162*)g_alo)[i4 * 2] = l0;
    ((__nv_bfloat162*)g_alo)[i4 * 2 + 1] = l1;
}

__global__ void final_k(const float* __restrict__ x, float* __restrict__ out) {
    __shared__ float s[32][33];
    int img = blockIdx.z, c0 = blockIdx.y * 32, p0 = blockIdx.x * 32;
    int tx = threadIdx.x, ty = threadIdx.y;
#pragma unroll
    for (int r = 0; r < 4; r++) {
        int pl = ty + r * 8;
        float v = g_buf2[((size_t)img * HWPIX + p0 + pl) * 256 + c0 + tx];
        s[pl][tx] = fmaf(v, g_bnscale[1][c0 + tx], g_bnshift[1][c0 + tx]);
    }
    __syncthreads();
#pragma unroll
    for (int r = 0; r < 4; r++) {
        int cl = ty + r * 8;
        size_t o = ((size_t)img * 256 + c0 + cl) * HWPIX + p0 + tx;
        out[o] = fmaxf(s[tx][cl] + x[o], 0.f);
    }
}

// ------------------------------------------------------------------------------
extern "C" void kernel_launch(void* const* d_in, const int* in_sizes, int n_in,
                              void* d_out, int out_size) {
    const float* x  = (const float*)d_in[0];
    const float* w1 = (const float*)d_in[1];
    const float* g1 = (const float*)d_in[2];
    const float* b1 = (const float*)d_in[3];
    const float* w2 = (const float*)d_in[4];
    const float* g2 = (const float*)d_in[5];
    const float* b2 = (const float*)d_in[6];
    float* out = (float*)d_out;

    cudaFuncSetAttribute(conv_k, cudaFuncAttributeMaxDynamicSharedMemorySize, SMSZ);

    init_k<<<1, 256>>>();                                   // 1
    absmax3_k<<<dim3(320, 3), 256>>>(w1, w2, x);            // 2
    prep_k<<<1024 + 64 * 784, 256>>>(w1, w2, x);            // 3
    dim3 cgrid(28, 2, 64);
    conv_k<<<cgrid, 256, SMSZ>>>(0);                        // 4  <- profiled
    bnstat_k<<<256, 256>>>(0);
    bnfin_k<<<1, 256>>>(g1, b1, 0);
    actprep_k<<<50176, 256>>>();
    conv_k<<<cgrid, 256, SMSZ>>>(1);
    bnstat_k<<<256, 256>>>(1);
    bnfin_k<<<1, 256>>>(g2, b2, 1);
    final_k<<<dim3(98, 8, 64), dim3(32, 8)>>>(x, out);
}